// round 3
// baseline (speedup 1.0000x reference)
#include <cuda_runtime.h>
#include <math.h>

#define NEG_SLOPE 0.1f

// Scratch for per-batch dynamic kernels and attention (alloc-free rule: __device__ globals)
__device__ float g_kern[16 * 576];   // [b][c*9 + i*3 + j]
__device__ float g_att [16 * 64];    // [b][o]

__device__ __forceinline__ float lrelu(float x) { return x >= 0.f ? x : NEG_SLOPE * x; }

// ---- f32x2 packed helpers (sm_103a FFMA2 path) ----
__device__ __forceinline__ unsigned long long pk2(float lo, float hi) {
    unsigned long long r;
    asm("mov.b64 %0, {%1, %2};" : "=l"(r) : "f"(lo), "f"(hi));
    return r;
}
__device__ __forceinline__ void upk2(unsigned long long v, float& lo, float& hi) {
    asm("mov.b64 {%0, %1}, %2;" : "=f"(lo), "=f"(hi) : "l"(v));
}
__device__ __forceinline__ unsigned long long ffma2(unsigned long long a,
                                                    unsigned long long b,
                                                    unsigned long long c) {
    unsigned long long d;
    asm("fma.rn.f32x2 %0, %1, %2, %3;" : "=l"(d) : "l"(a), "l"(b), "l"(c));
    return d;
}

// ============================================================================
// Kernel A: per-batch vectors.
//   dvec = mean(deg, HW)           [512]
//   f    = dvec @ W_size^T         [64]
//   kern = lrelu(f @ W_k1^T) @ W_k2^T            -> g_kern [576]
//   fa   = dvec @ W_ac^T           [64]
//   att  = sigmoid(lrelu(fa @ W_du1^T) @ W_du2^T) -> g_att [64]
// grid = 16 (one block per batch), 512 threads
// ============================================================================
__global__ void __launch_bounds__(512) prep_kernel(
    const float* __restrict__ deg,     // [16,512,8,8]
    const float* __restrict__ W_size,  // [64,512]
    const float* __restrict__ W_k1,    // [8,64]
    const float* __restrict__ W_k2,    // [576,8]
    const float* __restrict__ W_ac,    // [64,512]
    const float* __restrict__ W_du1,   // [8,64]
    const float* __restrict__ W_du2)   // [64,8]
{
    const int b    = blockIdx.x;
    const int tid  = threadIdx.x;
    const int lane = tid & 31;
    const int wid  = tid >> 5;   // 0..15

    __shared__ float dvecS[512];
    __shared__ float partF[512];   // [p][c] = [8][64]
    __shared__ float partA[512];
    __shared__ float fS[64], faS[64];
    __shared__ float hS[8], hdS[8];

    // --- dvec: warp-cooperative mean over 64 elems, coalesced loads ---
    const float* degb = deg + (size_t)b * 512 * 64;
    for (int d = wid; d < 512; d += 16) {
        float s = degb[d * 64 + lane] + degb[d * 64 + lane + 32];
        #pragma unroll
        for (int off = 16; off > 0; off >>= 1)
            s += __shfl_xor_sync(0xffffffffu, s, off);
        if (lane == 0) dvecS[d] = s * (1.0f / 64.0f);
    }
    __syncthreads();

    // --- f, fa: split-K over 8 partials ---
    {
        const int p = tid >> 6;     // 0..7
        const int c = tid & 63;
        const int base = p * 64;
        float sf = 0.f, sa = 0.f;
        #pragma unroll 4
        for (int dd = 0; dd < 64; ++dd) {
            float x = dvecS[base + dd];
            sf = fmaf(x, W_size[c * 512 + base + dd], sf);
            sa = fmaf(x, W_ac  [c * 512 + base + dd], sa);
        }
        partF[p * 64 + c] = sf;
        partA[p * 64 + c] = sa;
    }
    __syncthreads();
    if (tid < 64) {
        float sf = 0.f, sa = 0.f;
        #pragma unroll
        for (int p = 0; p < 8; ++p) { sf += partF[p * 64 + tid]; sa += partA[p * 64 + tid]; }
        fS[tid] = sf;
        faS[tid] = sa;
    }
    __syncthreads();

    // --- hidden layers (8-wide) ---
    if (tid < 8) {
        float s = 0.f;
        #pragma unroll 8
        for (int c = 0; c < 64; ++c) s = fmaf(fS[c], W_k1[tid * 64 + c], s);
        hS[tid] = lrelu(s);
    } else if (tid >= 32 && tid < 40) {
        const int j = tid - 32;
        float s = 0.f;
        #pragma unroll 8
        for (int c = 0; c < 64; ++c) s = fmaf(faS[c], W_du1[j * 64 + c], s);
        hdS[j] = lrelu(s);
    }
    __syncthreads();

    // --- kern (no activation) and att ---
    for (int i = tid; i < 576; i += 512) {
        float s = 0.f;
        #pragma unroll
        for (int j = 0; j < 8; ++j) s = fmaf(hS[j], W_k2[i * 8 + j], s);
        g_kern[b * 576 + i] = s;
    }
    if (tid < 64) {
        float s = 0.f;
        #pragma unroll
        for (int j = 0; j < 8; ++j) s = fmaf(hdS[j], W_du2[tid * 8 + j], s);
        g_att[b * 64 + tid] = 1.0f / (1.0f + expf(-s));
    }
}

// ============================================================================
// Kernel B: fused depthwise-3x3 + lrelu + 1x1 channel mix + bias + feat*att.
// One block per (b, output row h). 512 threads.
//   Stage 1: dw[c][w] (64x128) in smem, computed from global feat rows (float4
//            loads + shfl for halo).
//   Stage 2: out[o][w] = sum_c Wt[c][o]*dw[c][w] + bias[o] + feat[o]*att[o],
//            register-tiled 4o x 4w per thread, FFMA2 (f32x2) inner loop.
// grid = 16*128 = 2048
// ============================================================================
__global__ void __launch_bounds__(512) main_kernel(
    const float* __restrict__ feat,    // [16,64,128,128]
    const float* __restrict__ W_conv,  // [64,64]  (row = out channel)
    const float* __restrict__ b_conv,  // [64]
    float* __restrict__ out)           // [16,64,128,128]
{
    __shared__ __align__(16) float dwS[64 * 128];   // 32 KB: dw[c][w]
    __shared__ __align__(16) float WtS[64 * 64];    // 16 KB: Wt[c][o] (transposed)
    __shared__ float kS[576];
    __shared__ float attS[64];
    __shared__ float biasS[64];

    const int tid  = threadIdx.x;
    const int bid  = blockIdx.x;
    const int b    = bid >> 7;
    const int h    = bid & 127;
    const int lane = tid & 31;
    const int wid  = tid >> 5;   // 0..15

    // --- stage shared operands ---
    for (int i = tid; i < 4096; i += 512) {
        int c = i >> 6, o = i & 63;
        WtS[c * 64 + o] = W_conv[o * 64 + c];
    }
    for (int i = tid; i < 576; i += 512) kS[i] = g_kern[b * 576 + i];
    if (tid < 64) { attS[tid] = g_att[b * 64 + tid]; biasS[tid] = b_conv[tid]; }
    __syncthreads();

    // --- Stage 1: depthwise 3x3 + lrelu into dwS ---
    const float4* feat4 = (const float4*)feat;
    #pragma unroll
    for (int cp = 0; cp < 4; ++cp) {
        const int c = cp * 16 + wid;
        float4 a = make_float4(0.f, 0.f, 0.f, 0.f);
        #pragma unroll
        for (int ri = 0; ri < 3; ++ri) {
            const int r = h - 1 + ri;
            float4 v;
            if (r >= 0 && r < 128)
                v = feat4[(((size_t)b * 64 + c) * 128 + r) * 32 + lane];
            else
                v = make_float4(0.f, 0.f, 0.f, 0.f);
            float left  = __shfl_up_sync(0xffffffffu, v.w, 1);
            float right = __shfl_down_sync(0xffffffffu, v.x, 1);
            if (lane == 0)  left  = 0.f;
            if (lane == 31) right = 0.f;
            const float q0 = kS[c * 9 + ri * 3 + 0];
            const float q1 = kS[c * 9 + ri * 3 + 1];
            const float q2 = kS[c * 9 + ri * 3 + 2];
            a.x = fmaf(q0, left, fmaf(q1, v.x, fmaf(q2, v.y,  a.x)));
            a.y = fmaf(q0, v.x,  fmaf(q1, v.y, fmaf(q2, v.z,  a.y)));
            a.z = fmaf(q0, v.y,  fmaf(q1, v.z, fmaf(q2, v.w,  a.z)));
            a.w = fmaf(q0, v.z,  fmaf(q1, v.w, fmaf(q2, right, a.w)));
        }
        a.x = lrelu(a.x); a.y = lrelu(a.y); a.z = lrelu(a.z); a.w = lrelu(a.w);
        ((float4*)dwS)[c * 32 + lane] = a;
    }
    __syncthreads();

    // --- Stage 2: 1x1 mix, 4 output channels x 4 pixels per thread, FFMA2 ---
    const int o_t = tid >> 5;   // 0..15 -> o0 = 4*o_t
    const int w_t = tid & 31;   // 0..31 -> w0 = 4*w_t
    const int o0  = o_t * 4;

    unsigned long long acc[4][2];
    #pragma unroll
    for (int i = 0; i < 4; ++i) { acc[i][0] = 0ull; acc[i][1] = 0ull; }

    const ulonglong2* dw2 = (const ulonglong2*)dwS;   // dw[c][w0..w3] as 2 packed pairs
    const float4*     wt4 = (const float4*)WtS;       // Wt[c][o0..o3]

    #pragma unroll 4
    for (int c = 0; c < 64; ++c) {
        ulonglong2 d = dw2[c * 16 + w_t];             // {w0,w1},{w2,w3}
        float4 wv    = wt4[c * 16 + o_t];             // broadcast within warp
        unsigned long long wp0 = pk2(wv.x, wv.x);
        unsigned long long wp1 = pk2(wv.y, wv.y);
        unsigned long long wp2 = pk2(wv.z, wv.z);
        unsigned long long wp3 = pk2(wv.w, wv.w);
        acc[0][0] = ffma2(wp0, d.x, acc[0][0]);
        acc[0][1] = ffma2(wp0, d.y, acc[0][1]);
        acc[1][0] = ffma2(wp1, d.x, acc[1][0]);
        acc[1][1] = ffma2(wp1, d.y, acc[1][1]);
        acc[2][0] = ffma2(wp2, d.x, acc[2][0]);
        acc[2][1] = ffma2(wp2, d.y, acc[2][1]);
        acc[3][0] = ffma2(wp3, d.x, acc[3][0]);
        acc[3][1] = ffma2(wp3, d.y, acc[3][1]);
    }

    // --- epilogue: + bias + feat*att, coalesced float4 stores ---
    #pragma unroll
    for (int oo = 0; oo < 4; ++oo) {
        const int o = o0 + oo;
        float r0, r1, r2, r3;
        upk2(acc[oo][0], r0, r1);
        upk2(acc[oo][1], r2, r3);
        const float bb = biasS[o];
        const float aa = attS[o];
        const size_t idx4 = (((size_t)b * 64 + o) * 128 + h) * 32 + w_t;
        float4 fv = ((const float4*)feat)[idx4];
        float4 ov;
        ov.x = r0 + bb + fv.x * aa;
        ov.y = r1 + bb + fv.y * aa;
        ov.z = r2 + bb + fv.z * aa;
        ov.w = r3 + bb + fv.w * aa;
        ((float4*)out)[idx4] = ov;
    }
}

extern "C" void kernel_launch(void* const* d_in, const int* in_sizes, int n_in,
                              void* d_out, int out_size) {
    (void)in_sizes; (void)n_in; (void)out_size;
    const float* feat   = (const float*)d_in[0];
    const float* deg    = (const float*)d_in[1];
    const float* W_size = (const float*)d_in[2];
    const float* W_k1   = (const float*)d_in[3];
    const float* W_k2   = (const float*)d_in[4];
    const float* W_conv = (const float*)d_in[5];
    const float* b_conv = (const float*)d_in[6];
    const float* W_ac   = (const float*)d_in[7];
    const float* W_du1  = (const float*)d_in[8];
    const float* W_du2  = (const float*)d_in[9];
    float* out = (float*)d_out;

    prep_kernel<<<16, 512>>>(deg, W_size, W_k1, W_k2, W_ac, W_du1, W_du2);
    main_kernel<<<16 * 128, 512>>>(feat, W_conv, b_conv, out);
}

// round 9
// speedup vs baseline: 1.2832x; 1.2832x over previous
#include <cuda_runtime.h>
#include <math.h>

#define NEG_SLOPE 0.1f

// Scratch (__device__ globals: alloc-free rule)
__device__ float g_dvec[16 * 512];
__device__ float g_kern[16 * 576];   // [b][c*9 + i*3 + j]
__device__ float g_att [16 * 64];

__device__ __forceinline__ float lrelu(float x) { return x >= 0.f ? x : NEG_SLOPE * x; }

// ---- f32x2 packed helpers (sm_103a FFMA2) ----
__device__ __forceinline__ unsigned long long pk2(float lo, float hi) {
    unsigned long long r;
    asm("mov.b64 %0, {%1, %2};" : "=l"(r) : "f"(lo), "f"(hi));
    return r;
}
__device__ __forceinline__ void upk2(unsigned long long v, float& lo, float& hi) {
    asm("mov.b64 {%0, %1}, %2;" : "=f"(lo), "=f"(hi) : "l"(v));
}
__device__ __forceinline__ unsigned long long ffma2(unsigned long long a,
                                                    unsigned long long b,
                                                    unsigned long long c) {
    unsigned long long d;
    asm("fma.rn.f32x2 %0, %1, %2, %3;" : "=l"(d) : "l"(a), "l"(b), "l"(c));
    return d;
}

// ============================================================================
// Kernel A1: dvec = mean(deg over 8x8).  128 blocks x 256 threads,
// warp-per-(b,d) row, 8 rows per warp. DRAM-bound (~2 MB), ~2-3 us.
// ============================================================================
__global__ void __launch_bounds__(256) mean_kernel(const float* __restrict__ deg)
{
    const int lane = threadIdx.x & 31;
    const int gw   = (blockIdx.x * 256 + threadIdx.x) >> 5;   // 0..1023
    #pragma unroll
    for (int i = 0; i < 8; ++i) {
        const int task = gw + i * 1024;          // 0..8191
        const int b = task >> 9;
        const int d = task & 511;
        const float* p = deg + ((size_t)b * 512 + d) * 64;
        float s = p[lane] + p[lane + 32];
        #pragma unroll
        for (int off = 16; off > 0; off >>= 1)
            s += __shfl_xor_sync(0xffffffffu, s, off);
        if (lane == 0) g_dvec[b * 512 + d] = s * (1.0f / 64.0f);
    }
}

// ============================================================================
// Kernel A2: GEMV chains -> g_kern, g_att.  16 blocks x 512 threads.
// ============================================================================
__global__ void __launch_bounds__(512) prep_kernel(
    const float* __restrict__ W_size,  // [64,512]
    const float* __restrict__ W_k1,    // [8,64]
    const float* __restrict__ W_k2,    // [576,8]
    const float* __restrict__ W_ac,    // [64,512]
    const float* __restrict__ W_du1,   // [8,64]
    const float* __restrict__ W_du2)   // [64,8]
{
    const int b   = blockIdx.x;
    const int tid = threadIdx.x;

    __shared__ float dvecS[512];
    __shared__ float partF[512];   // [p][c] = [8][64]
    __shared__ float partA[512];
    __shared__ float fS[64], faS[64];
    __shared__ float hS[8], hdS[8];

    dvecS[tid] = g_dvec[b * 512 + tid];
    __syncthreads();

    // f, fa: split-K over 8 partials
    {
        const int p = tid >> 6;     // 0..7
        const int c = tid & 63;
        const int base = p * 64;
        float sf = 0.f, sa = 0.f;
        #pragma unroll 8
        for (int dd = 0; dd < 64; ++dd) {
            float x = dvecS[base + dd];
            sf = fmaf(x, W_size[c * 512 + base + dd], sf);
            sa = fmaf(x, W_ac  [c * 512 + base + dd], sa);
        }
        partF[p * 64 + c] = sf;
        partA[p * 64 + c] = sa;
    }
    __syncthreads();
    if (tid < 64) {
        float sf = 0.f, sa = 0.f;
        #pragma unroll
        for (int p = 0; p < 8; ++p) { sf += partF[p * 64 + tid]; sa += partA[p * 64 + tid]; }
        fS[tid] = sf;
        faS[tid] = sa;
    }
    __syncthreads();

    if (tid < 8) {
        float s = 0.f;
        #pragma unroll 16
        for (int c = 0; c < 64; ++c) s = fmaf(fS[c], W_k1[tid * 64 + c], s);
        hS[tid] = lrelu(s);
    } else if (tid >= 32 && tid < 40) {
        const int j = tid - 32;
        float s = 0.f;
        #pragma unroll 16
        for (int c = 0; c < 64; ++c) s = fmaf(faS[c], W_du1[j * 64 + c], s);
        hdS[j] = lrelu(s);
    }
    __syncthreads();

    for (int i = tid; i < 576; i += 512) {
        float s = 0.f;
        #pragma unroll
        for (int j = 0; j < 8; ++j) s = fmaf(hS[j], W_k2[i * 8 + j], s);
        g_kern[b * 576 + i] = s;
    }
    if (tid < 64) {
        float s = 0.f;
        #pragma unroll
        for (int j = 0; j < 8; ++j) s = fmaf(hdS[j], W_du2[tid * 8 + j], s);
        g_att[b * 64 + tid] = 1.0f / (1.0f + expf(-s));
    }
}

// ============================================================================
// Kernel B: fused depthwise-3x3 + lrelu + 1x1 mix + bias + feat*att.
// Block = (b, 2 output rows). 512 threads. Dynamic smem 84.7 KB (2 CTA/SM).
//   Stage 1: dw[row][c][w] for 2 rows; 4 input rows loaded (halo shared).
//   Stage 2: 8o x 4w per thread per row, FFMA2 inner loop. Weight loads are
//            warp-uniform broadcasts -> crossbar traffic is dwS only.
// grid = 16*64 = 1024
// ============================================================================
__global__ void __launch_bounds__(512, 2) main_kernel(
    const float* __restrict__ feat,    // [16,64,128,128]
    const float* __restrict__ W_conv,  // [64,64]
    const float* __restrict__ b_conv,  // [64]
    float* __restrict__ out)
{
    extern __shared__ float smemF[];
    float* dwS   = smemF;            // [2][64][128] = 16384 floats
    float* WtS   = smemF + 16384;    // [c][o] 4096 floats
    float* kS    = smemF + 20480;    // 576
    float* attS  = smemF + 21056;    // 64
    float* biasS = smemF + 21120;    // 64

    const int tid  = threadIdx.x;
    const int bid  = blockIdx.x;
    const int b    = bid >> 6;
    const int h0   = (bid & 63) * 2;
    const int lane = tid & 31;
    const int wid  = tid >> 5;   // 0..15

    // --- stage shared operands ---
    for (int i = tid; i < 4096; i += 512) {
        int c = i >> 6, o = i & 63;
        WtS[c * 64 + o] = W_conv[o * 64 + c];
    }
    for (int i = tid; i < 576; i += 512) kS[i] = g_kern[b * 576 + i];
    if (tid < 64) { attS[tid] = g_att[b * 64 + tid]; biasS[tid] = b_conv[tid]; }
    __syncthreads();

    // --- Stage 1: depthwise 3x3 + lrelu for both rows ---
    const float4* feat4 = (const float4*)feat;
    #pragma unroll
    for (int cp = 0; cp < 4; ++cp) {
        const int c = cp * 16 + wid;
        float4 v[4];
        float lf[4], rg[4];
        #pragma unroll
        for (int ri = 0; ri < 4; ++ri) {
            const int r = h0 - 1 + ri;
            if (r >= 0 && r < 128)
                v[ri] = feat4[(((size_t)b * 64 + c) * 128 + r) * 32 + lane];
            else
                v[ri] = make_float4(0.f, 0.f, 0.f, 0.f);
            lf[ri] = __shfl_up_sync(0xffffffffu, v[ri].w, 1);
            rg[ri] = __shfl_down_sync(0xffffffffu, v[ri].x, 1);
            if (lane == 0)  lf[ri] = 0.f;
            if (lane == 31) rg[ri] = 0.f;
        }
        #pragma unroll
        for (int row = 0; row < 2; ++row) {
            float4 a = make_float4(0.f, 0.f, 0.f, 0.f);
            #pragma unroll
            for (int kr = 0; kr < 3; ++kr) {
                const int ri = row + kr;
                const float q0 = kS[c * 9 + kr * 3 + 0];
                const float q1 = kS[c * 9 + kr * 3 + 1];
                const float q2 = kS[c * 9 + kr * 3 + 2];
                a.x = fmaf(q0, lf[ri],   fmaf(q1, v[ri].x, fmaf(q2, v[ri].y, a.x)));
                a.y = fmaf(q0, v[ri].x,  fmaf(q1, v[ri].y, fmaf(q2, v[ri].z, a.y)));
                a.z = fmaf(q0, v[ri].y,  fmaf(q1, v[ri].z, fmaf(q2, v[ri].w, a.z)));
                a.w = fmaf(q0, v[ri].z,  fmaf(q1, v[ri].w, fmaf(q2, rg[ri],  a.w)));
            }
            a.x = lrelu(a.x); a.y = lrelu(a.y); a.z = lrelu(a.z); a.w = lrelu(a.w);
            ((float4*)(dwS + row * 8192))[c * 32 + lane] = a;
        }
    }
    __syncthreads();

    // --- Stage 2: 1x1 mix, 8 o-channels x 4 pixels per thread, one row each ---
    const int w_t = tid & 31;          // pixel group (4 px)
    const int og  = (tid >> 5) & 7;    // o0 = og*8   (warp-uniform)
    const int row = tid >> 8;          // 0/1         (warp-uniform)
    const int o0  = og * 8;
    const int h   = h0 + row;

    const ulonglong2* dw2 = (const ulonglong2*)(dwS + row * 8192);
    const float4*     wt4 = (const float4*)WtS;

    unsigned long long acc[8][2];
    #pragma unroll
    for (int i = 0; i < 8; ++i) { acc[i][0] = 0ull; acc[i][1] = 0ull; }

    #pragma unroll 4
    for (int c = 0; c < 64; ++c) {
        ulonglong2 d = dw2[c * 16 + w_t];           // {w0,w1},{w2,w3}
        float4 wa = wt4[c * 16 + og * 2];           // o0..o3 (broadcast)
        float4 wb = wt4[c * 16 + og * 2 + 1];       // o4..o7 (broadcast)
        unsigned long long p;
        p = pk2(wa.x, wa.x); acc[0][0] = ffma2(p, d.x, acc[0][0]); acc[0][1] = ffma2(p, d.y, acc[0][1]);
        p = pk2(wa.y, wa.y); acc[1][0] = ffma2(p, d.x, acc[1][0]); acc[1][1] = ffma2(p, d.y, acc[1][1]);
        p = pk2(wa.z, wa.z); acc[2][0] = ffma2(p, d.x, acc[2][0]); acc[2][1] = ffma2(p, d.y, acc[2][1]);
        p = pk2(wa.w, wa.w); acc[3][0] = ffma2(p, d.x, acc[3][0]); acc[3][1] = ffma2(p, d.y, acc[3][1]);
        p = pk2(wb.x, wb.x); acc[4][0] = ffma2(p, d.x, acc[4][0]); acc[4][1] = ffma2(p, d.y, acc[4][1]);
        p = pk2(wb.y, wb.y); acc[5][0] = ffma2(p, d.x, acc[5][0]); acc[5][1] = ffma2(p, d.y, acc[5][1]);
        p = pk2(wb.z, wb.z); acc[6][0] = ffma2(p, d.x, acc[6][0]); acc[6][1] = ffma2(p, d.y, acc[6][1]);
        p = pk2(wb.w, wb.w); acc[7][0] = ffma2(p, d.x, acc[7][0]); acc[7][1] = ffma2(p, d.y, acc[7][1]);
    }

    // --- epilogue: + bias + feat*att, coalesced float4 stores ---
    #pragma unroll
    for (int oo = 0; oo < 8; ++oo) {
        const int o = o0 + oo;
        float r0, r1, r2, r3;
        upk2(acc[oo][0], r0, r1);
        upk2(acc[oo][1], r2, r3);
        const float bb = biasS[o];
        const float aa = attS[o];
        const size_t idx4 = (((size_t)b * 64 + o) * 128 + h) * 32 + w_t;
        float4 fv = ((const float4*)feat)[idx4];
        float4 ov;
        ov.x = r0 + bb + fv.x * aa;
        ov.y = r1 + bb + fv.y * aa;
        ov.z = r2 + bb + fv.z * aa;
        ov.w = r3 + bb + fv.w * aa;
        ((float4*)out)[idx4] = ov;
    }
}

extern "C" void kernel_launch(void* const* d_in, const int* in_sizes, int n_in,
                              void* d_out, int out_size) {
    (void)in_sizes; (void)n_in; (void)out_size;
    const float* feat   = (const float*)d_in[0];
    const float* deg    = (const float*)d_in[1];
    const float* W_size = (const float*)d_in[2];
    const float* W_k1   = (const float*)d_in[3];
    const float* W_k2   = (const float*)d_in[4];
    const float* W_conv = (const float*)d_in[5];
    const float* b_conv = (const float*)d_in[6];
    const float* W_ac   = (const float*)d_in[7];
    const float* W_du1  = (const float*)d_in[8];
    const float* W_du2  = (const float*)d_in[9];
    float* out = (float*)d_out;

    const int kMainSmem = 21184 * 4;   // 84736 B
    (void)cudaFuncSetAttribute(main_kernel,
                               cudaFuncAttributeMaxDynamicSharedMemorySize, kMainSmem);

    mean_kernel<<<128, 256>>>(deg);
    prep_kernel<<<16, 512>>>(W_size, W_k1, W_k2, W_ac, W_du1, W_du2);
    main_kernel<<<16 * 64, 512, kMainSmem>>>(feat, W_conv, b_conv, out);
}